// round 3
// baseline (speedup 1.0000x reference)
#include <cuda_runtime.h>
#include <cstdint>

#define BATCH  4096
#define DIM    1024
#define TDICT  32768
#define TOPK   64
#define G0_END 2048
#define G1_END 8192

typedef unsigned long long ull;

// ---------------- scratch (device globals: allocation-free) ----------------
static __device__ float g_acts[(size_t)BATCH * TDICT];   // 512 MB relu'd pre-acts
static __device__ float g_topv[BATCH * TOPK];
static __device__ int   g_topi[BATCH * TOPK];

__device__ __forceinline__ void ffma2(ull& d, ull a, ull b) {
    asm("fma.rn.f32x2 %0, %1, %2, %0;" : "+l"(d) : "l"(a), "l"(b));
}
__device__ __forceinline__ float lo32(ull v) { return __uint_as_float((unsigned)(v & 0xffffffffULL)); }
__device__ __forceinline__ float hi32(ull v) { return __uint_as_float((unsigned)(v >> 32)); }

// ============================================================================
// Kernel 1: encoder GEMM  g_acts = relu((x - b_dec) @ W_enc + b_enc)
// 128x128 tile, BK=8, 256 threads, 8x8 per thread, packed f32x2 FMA.
// A tile stored DUPLICATED along m so packed A operands come straight from LDS.
// ============================================================================
__global__ void __launch_bounds__(256, 2)
enc_gemm_relu(const float* __restrict__ X, const float* __restrict__ W,
              const float* __restrict__ Benc, const float* __restrict__ Bdec)
{
    __shared__ float As[2][8][264];   // duplicated: 256 live floats + pad
    __shared__ float Bs[2][8][128];

    const int tid = threadIdx.x;
    const int bm = blockIdx.y, bn = blockIdx.x;

    const int aRow = tid >> 1;          // 0..127
    const int aCol = (tid & 1) << 2;    // 0 or 4
    const int bRow = tid >> 5;          // 0..7
    const int bCol = (tid & 31) << 2;   // 0..124

    const float* Ap  = X + (size_t)(bm * 128 + aRow) * DIM + aCol;
    const float* Bp  = W + (size_t)bRow * TDICT + (size_t)bn * 128 + bCol;
    const float* BdP = Bdec + aCol;

    float4 a = *(const float4*)Ap;
    float4 d = *(const float4*)BdP;
    float4 b = *(const float4*)Bp;
    a.x -= d.x; a.y -= d.y; a.z -= d.z; a.w -= d.w;

    *(float2*)&As[0][aCol + 0][2 * aRow] = make_float2(a.x, a.x);
    *(float2*)&As[0][aCol + 1][2 * aRow] = make_float2(a.y, a.y);
    *(float2*)&As[0][aCol + 2][2 * aRow] = make_float2(a.z, a.z);
    *(float2*)&As[0][aCol + 3][2 * aRow] = make_float2(a.w, a.w);
    *(float4*)&Bs[0][bRow][bCol] = b;
    __syncthreads();

    ull acc[8][4];
    #pragma unroll
    for (int i = 0; i < 8; i++) {
        #pragma unroll
        for (int j = 0; j < 4; j++) acc[i][j] = 0ULL;
    }

    const int m0 = (tid >> 4) << 3;   // 0..120
    const int n0 = (tid & 15) << 3;   // 0..120

    int buf = 0;
    #pragma unroll 1
    for (int kt = 0; kt < 128; kt++) {
        if (kt < 127) {
            a = *(const float4*)(Ap + (kt + 1) * 8);
            d = *(const float4*)(BdP + (kt + 1) * 8);
            b = *(const float4*)(Bp + (size_t)(kt + 1) * 8 * TDICT);
        }
        #pragma unroll
        for (int k = 0; k < 8; k++) {
            ulonglong2 a01 = *(const ulonglong2*)&As[buf][k][2 * m0];
            ulonglong2 a23 = *(const ulonglong2*)&As[buf][k][2 * m0 + 4];
            ulonglong2 a45 = *(const ulonglong2*)&As[buf][k][2 * m0 + 8];
            ulonglong2 a67 = *(const ulonglong2*)&As[buf][k][2 * m0 + 12];
            ulonglong2 b03 = *(const ulonglong2*)&Bs[buf][k][n0];
            ulonglong2 b47 = *(const ulonglong2*)&Bs[buf][k][n0 + 4];
            ull ap[8]; ull bp[4];
            ap[0] = a01.x; ap[1] = a01.y; ap[2] = a23.x; ap[3] = a23.y;
            ap[4] = a45.x; ap[5] = a45.y; ap[6] = a67.x; ap[7] = a67.y;
            bp[0] = b03.x; bp[1] = b03.y; bp[2] = b47.x; bp[3] = b47.y;
            #pragma unroll
            for (int i = 0; i < 8; i++) {
                #pragma unroll
                for (int j = 0; j < 4; j++) ffma2(acc[i][j], ap[i], bp[j]);
            }
        }
        if (kt < 127) {
            buf ^= 1;
            a.x -= d.x; a.y -= d.y; a.z -= d.z; a.w -= d.w;
            *(float2*)&As[buf][aCol + 0][2 * aRow] = make_float2(a.x, a.x);
            *(float2*)&As[buf][aCol + 1][2 * aRow] = make_float2(a.y, a.y);
            *(float2*)&As[buf][aCol + 2][2 * aRow] = make_float2(a.z, a.z);
            *(float2*)&As[buf][aCol + 3][2 * aRow] = make_float2(a.w, a.w);
            *(float4*)&Bs[buf][bRow][bCol] = b;
            __syncthreads();
        }
    }

    // epilogue: + b_enc, relu, store
    const float4 be0 = *(const float4*)(Benc + bn * 128 + n0);
    const float4 be1 = *(const float4*)(Benc + bn * 128 + n0 + 4);
    float* out = g_acts + (size_t)(bm * 128 + m0) * TDICT + bn * 128 + n0;
    #pragma unroll
    for (int i = 0; i < 8; i++) {
        float4 r0, r1;
        r0.x = fmaxf(lo32(acc[i][0]) + be0.x, 0.f);
        r0.y = fmaxf(hi32(acc[i][0]) + be0.y, 0.f);
        r0.z = fmaxf(lo32(acc[i][1]) + be0.z, 0.f);
        r0.w = fmaxf(hi32(acc[i][1]) + be0.w, 0.f);
        r1.x = fmaxf(lo32(acc[i][2]) + be1.x, 0.f);
        r1.y = fmaxf(hi32(acc[i][2]) + be1.y, 0.f);
        r1.z = fmaxf(lo32(acc[i][3]) + be1.z, 0.f);
        r1.w = fmaxf(hi32(acc[i][3]) + be1.w, 0.f);
        *(float4*)(out + (size_t)i * TDICT)     = r0;
        *(float4*)(out + (size_t)i * TDICT + 4) = r1;
    }
}

// ============================================================================
// Kernel 2: exact top-64 per row via 4-level radix select on float bits.
// Non-negative floats: bit pattern order == numeric order. Ties broken by
// lowest index (matches jax.lax.top_k). Output sorted by index (deterministic).
// ============================================================================
__global__ void __launch_bounds__(256)
topk_kernel()
{
    extern __shared__ unsigned int sv[];   // TDICT uints
    __shared__ unsigned int hist[256];
    __shared__ unsigned int s_prefix, s_outPos, s_eqCnt;
    __shared__ int s_k;
    __shared__ int  eqIdx[64];
    __shared__ float cv[64];
    __shared__ int   ci[64];

    const int row = blockIdx.x;
    const int tid = threadIdx.x;

    // load row bits into smem
    const float4* src4 = (const float4*)(g_acts + (size_t)row * TDICT);
    float4* dst4 = (float4*)sv;
    for (int j = tid; j < TDICT / 4; j += 256) dst4[j] = src4[j];

    if (tid == 0) { s_prefix = 0u; s_k = TOPK; s_outPos = 0u; s_eqCnt = 0u; }
    __syncthreads();

    // 4 radix levels, bytes high->low
    for (int shift = 24; shift >= 0; shift -= 8) {
        hist[tid] = 0u;
        if (tid < 256 - 256) {}   // (blockDim==256 covers all bins)
        __syncthreads();
        const unsigned int pfx = s_prefix;
        const unsigned int maskHigh = (shift == 24) ? 0u : (0xFFFFFFFFu << (shift + 8));
        for (int j = tid; j < TDICT; j += 256) {
            unsigned int v = sv[j];
            if ((v & maskHigh) == pfx) {
                unsigned int bin = (v >> shift) & 255u;
                unsigned int am = __activemask();
                unsigned int mk = __match_any_sync(am, bin);
                if ((tid & 31) == (__ffs(mk) - 1))
                    atomicAdd(&hist[bin], (unsigned)__popc(mk));
            }
        }
        __syncthreads();
        if (tid == 0) {
            int k = s_k, cum = 0, bin = 0;
            for (int b = 255; b >= 0; --b) {
                int h = (int)hist[b];
                if (cum + h >= k) { bin = b; break; }
                cum += h;
            }
            s_k = k - cum;
            s_prefix = pfx | ((unsigned)bin << shift);
        }
        __syncthreads();
    }

    const unsigned int pivot = s_prefix;   // exact bits of the 64th largest
    const int R = s_k;                     // entries at pivot value we still need

    // collect: strictly greater + equal candidates
    for (int j = tid; j < TDICT; j += 256) {
        unsigned int v = sv[j];
        if (v > pivot) {
            unsigned int p = atomicAdd(&s_outPos, 1u);
            cv[p] = __uint_as_float(v);
            ci[p] = j;
        } else if (v == pivot && pivot != 0u) {
            unsigned int q = atomicAdd(&s_eqCnt, 1u);
            if (q < 64u) eqIdx[q] = j;
        }
    }
    __syncthreads();

    if (tid == 0) {
        int base = TOPK - R;   // == number strictly greater
        if (pivot == 0u) {
            // remaining values are exactly zero -> contribution-free fillers
            for (int r = 0; r < R; ++r) { cv[base + r] = 0.f; ci[base + r] = TDICT + r; }
        } else {
            int n = (int)s_eqCnt; if (n > 64) n = 64;
            for (int r = 0; r < R; ++r) {        // pick R smallest indices
                int best = 0x7fffffff, bi = -1;
                for (int t = 0; t < n; ++t)
                    if (eqIdx[t] < best) { best = eqIdx[t]; bi = t; }
                if (bi >= 0) eqIdx[bi] = 0x7fffffff;
                cv[base + r] = __uint_as_float(pivot);
                ci[base + r] = best;
            }
        }
    }
    __syncthreads();

    // rank-sort the 64 entries by index (all real indices distinct; fillers distinct)
    if (tid < TOPK) {
        int myIdx = ci[tid]; float myV = cv[tid];
        int rank = 0;
        #pragma unroll 8
        for (int u = 0; u < TOPK; ++u) {
            int o = ci[u];
            if (o < myIdx || (o == myIdx && u < tid)) rank++;
        }
        g_topv[row * TOPK + rank] = myV;
        g_topi[row * TOPK + rank] = (myIdx < TDICT) ? myIdx : 0;
    }
}

// ============================================================================
// Kernel 3: nested (matryoshka) sparse decode.
// out[g][b] = b_dec + sum over topk entries with idx < bounds[g+1] of v*W_dec[idx]
// ============================================================================
__global__ void __launch_bounds__(256)
decode_kernel(const float* __restrict__ Wdec, const float* __restrict__ Bdec,
              float* __restrict__ out)
{
    const int row = blockIdx.x;
    const int tid = threadIdx.x;
    __shared__ float sv[TOPK];
    __shared__ int   si[TOPK];
    if (tid < TOPK) {
        sv[tid] = g_topv[row * TOPK + tid];
        si[tid] = g_topi[row * TOPK + tid];
    }
    __syncthreads();

    const int d = tid * 4;
    float4 a0 = make_float4(0.f, 0.f, 0.f, 0.f);
    float4 a1 = a0, a2 = a0;

    #pragma unroll 4
    for (int e = 0; e < TOPK; ++e) {
        float v = sv[e];
        if (v == 0.f) continue;                 // filler / zero entry
        int idx = si[e];
        float4 w = *(const float4*)(Wdec + (size_t)idx * DIM + d);
        if (idx < G0_END) {
            a0.x += v * w.x; a0.y += v * w.y; a0.z += v * w.z; a0.w += v * w.w;
        } else if (idx < G1_END) {
            a1.x += v * w.x; a1.y += v * w.y; a1.z += v * w.z; a1.w += v * w.w;
        } else {
            a2.x += v * w.x; a2.y += v * w.y; a2.z += v * w.z; a2.w += v * w.w;
        }
    }

    float4 bd = *(const float4*)(Bdec + d);
    float4 r0 = make_float4(bd.x + a0.x, bd.y + a0.y, bd.z + a0.z, bd.w + a0.w);
    float4 r1 = make_float4(r0.x + a1.x, r0.y + a1.y, r0.z + a1.z, r0.w + a1.w);
    float4 r2 = make_float4(r1.x + a2.x, r1.y + a2.y, r1.z + a2.z, r1.w + a2.w);

    const size_t stride = (size_t)BATCH * DIM;
    float* o = out + (size_t)row * DIM + d;
    *(float4*)(o)              = r0;
    *(float4*)(o + stride)     = r1;
    *(float4*)(o + 2 * stride) = r2;
}

// ============================================================================
extern "C" void kernel_launch(void* const* d_in, const int* in_sizes, int n_in,
                              void* d_out, int out_size)
{
    const float* x     = (const float*)d_in[0];   // [4096, 1024]
    const float* W_enc = (const float*)d_in[1];   // [1024, 32768]
    const float* b_enc = (const float*)d_in[2];   // [32768]
    const float* W_dec = (const float*)d_in[3];   // [32768, 1024]
    const float* b_dec = (const float*)d_in[4];   // [1024]
    float* out = (float*)d_out;                   // [3, 4096, 1024]

    (void)in_sizes; (void)n_in; (void)out_size;

    dim3 ggrid(TDICT / 128, BATCH / 128);
    enc_gemm_relu<<<ggrid, 256>>>(x, W_enc, b_enc, b_dec);

    cudaFuncSetAttribute(topk_kernel, cudaFuncAttributeMaxDynamicSharedMemorySize,
                         TDICT * (int)sizeof(unsigned int));
    topk_kernel<<<BATCH, 256, TDICT * sizeof(unsigned int)>>>();

    decode_kernel<<<BATCH, 256>>>(W_dec, b_dec, out);
}

// round 4
// speedup vs baseline: 1.8036x; 1.8036x over previous
#include <cuda_runtime.h>
#include <cstdint>

#define BATCH  4096
#define DIM    1024
#define TDICT  32768
#define TOPK   64
#define G0_END 2048
#define G1_END 8192

typedef unsigned long long ull;

// ---------------- scratch (device globals: allocation-free) ----------------
static __device__ float g_acts[(size_t)BATCH * TDICT];   // 512 MB relu'd pre-acts
static __device__ float g_topv[BATCH * TOPK];
static __device__ int   g_topi[BATCH * TOPK];

__device__ __forceinline__ void ffma2(ull& d, ull a, ull b) {
    asm("fma.rn.f32x2 %0, %1, %2, %0;" : "+l"(d) : "l"(a), "l"(b));
}
__device__ __forceinline__ ull dup2(float f) {
    ull r; asm("mov.b64 %0, {%1, %1};" : "=l"(r) : "f"(f)); return r;
}
__device__ __forceinline__ float lo32(ull v) { return __uint_as_float((unsigned)(v & 0xffffffffULL)); }
__device__ __forceinline__ float hi32(ull v) { return __uint_as_float((unsigned)(v >> 32)); }

// ============================================================================
// Kernel 1: encoder GEMM  g_acts = relu((x - b_dec) @ W_enc + b_enc)
// Block tile 256m x 128n, BK=8, 256 threads, per-thread 16m x 8n.
// Accumulators packed along m (f32x2 of adjacent m rows) -> A operands load
// packed straight from SMEM (no duplication). B broadcast pairs built with
// movs on the ALU pipe. SMEM traffic: 96 B per 64 FFMA2 per thread.
// ============================================================================
__global__ void __launch_bounds__(256, 1)
enc_gemm_relu(const float* __restrict__ X, const float* __restrict__ W,
              const float* __restrict__ Benc, const float* __restrict__ Bdec)
{
    __shared__ float As[2][8][260];   // [k][m], 256 live + pad
    __shared__ float Bs[2][8][132];   // [k][n], 128 live + pad

    const int tid = threadIdx.x;
    const int bm = blockIdx.x, bn = blockIdx.y;

    // A loader: thread covers rows ar and ar+128, k-halves ak..ak+3
    const int ar = tid >> 1;          // 0..127
    const int ak = (tid & 1) << 2;    // 0 or 4
    // B loader
    const int br = tid >> 5;          // 0..7
    const int bc = (tid & 31) << 2;   // 0..124

    const float* Ap0 = X + (size_t)(bm * 256 + ar) * DIM + ak;
    const float* Ap1 = Ap0 + (size_t)128 * DIM;
    const float* Bp  = W + (size_t)br * TDICT + bn * 128 + bc;

    float4 a0 = *(const float4*)Ap0;
    float4 a1 = *(const float4*)Ap1;
    float4 bd = *(const float4*)(Bdec + ak);
    float4 b  = *(const float4*)Bp;

    As[0][ak + 0][ar]       = a0.x - bd.x;
    As[0][ak + 1][ar]       = a0.y - bd.y;
    As[0][ak + 2][ar]       = a0.z - bd.z;
    As[0][ak + 3][ar]       = a0.w - bd.w;
    As[0][ak + 0][ar + 128] = a1.x - bd.x;
    As[0][ak + 1][ar + 128] = a1.y - bd.y;
    As[0][ak + 2][ar + 128] = a1.z - bd.z;
    As[0][ak + 3][ar + 128] = a1.w - bd.w;
    *(float4*)&Bs[0][br][bc] = b;
    __syncthreads();

    const int tm = (tid & 15) << 2;   // 0..60  (m quadrant offset)
    const int tn = (tid >> 4) << 3;   // 0..120

    ull acc[8][8];
    #pragma unroll
    for (int i = 0; i < 8; i++)
        #pragma unroll
        for (int j = 0; j < 8; j++) acc[i][j] = 0ULL;

    int buf = 0;
    #pragma unroll 1
    for (int kt = 0; kt < 128; ++kt) {
        if (kt < 127) {
            a0 = *(const float4*)(Ap0 + (kt + 1) * 8);
            a1 = *(const float4*)(Ap1 + (kt + 1) * 8);
            bd = *(const float4*)(Bdec + (kt + 1) * 8 + ak);
            b  = *(const float4*)(Bp + (size_t)(kt + 1) * 8 * TDICT);
        }
        #pragma unroll
        for (int k = 0; k < 8; ++k) {
            ulonglong2 A0 = *(const ulonglong2*)&As[buf][k][tm];
            ulonglong2 A1 = *(const ulonglong2*)&As[buf][k][tm + 64];
            ulonglong2 A2 = *(const ulonglong2*)&As[buf][k][tm + 128];
            ulonglong2 A3 = *(const ulonglong2*)&As[buf][k][tm + 192];
            float4 b0 = *(const float4*)&Bs[buf][k][tn];
            float4 b1 = *(const float4*)&Bs[buf][k][tn + 4];
            ull ap[8];
            ap[0] = A0.x; ap[1] = A0.y; ap[2] = A1.x; ap[3] = A1.y;
            ap[4] = A2.x; ap[5] = A2.y; ap[6] = A3.x; ap[7] = A3.y;
            ull bp[8];
            bp[0] = dup2(b0.x); bp[1] = dup2(b0.y);
            bp[2] = dup2(b0.z); bp[3] = dup2(b0.w);
            bp[4] = dup2(b1.x); bp[5] = dup2(b1.y);
            bp[6] = dup2(b1.z); bp[7] = dup2(b1.w);
            #pragma unroll
            for (int i = 0; i < 8; i++)
                #pragma unroll
                for (int j = 0; j < 8; j++) ffma2(acc[i][j], ap[i], bp[j]);
        }
        if (kt < 127) {
            buf ^= 1;
            As[buf][ak + 0][ar]       = a0.x - bd.x;
            As[buf][ak + 1][ar]       = a0.y - bd.y;
            As[buf][ak + 2][ar]       = a0.z - bd.z;
            As[buf][ak + 3][ar]       = a0.w - bd.w;
            As[buf][ak + 0][ar + 128] = a1.x - bd.x;
            As[buf][ak + 1][ar + 128] = a1.y - bd.y;
            As[buf][ak + 2][ar + 128] = a1.z - bd.z;
            As[buf][ak + 3][ar + 128] = a1.w - bd.w;
            *(float4*)&Bs[buf][br][bc] = b;
            __syncthreads();
        }
    }

    // epilogue: + b_enc, relu, store. acc[i][j]: rows m0=64*(i>>1)+tm+2*(i&1)
    // (lo half) and m0+1 (hi half), col = tn + j.
    const float4 be0 = *(const float4*)(Benc + bn * 128 + tn);
    const float4 be1 = *(const float4*)(Benc + bn * 128 + tn + 4);
    const float be[8] = {be0.x, be0.y, be0.z, be0.w, be1.x, be1.y, be1.z, be1.w};
    #pragma unroll
    for (int i = 0; i < 8; i++) {
        const int m0 = ((i >> 1) << 6) + tm + ((i & 1) << 1);
        float* out0 = g_acts + (size_t)(bm * 256 + m0) * TDICT + bn * 128 + tn;
        float* out1 = out0 + TDICT;
        float4 r0, r1, s0, s1;
        r0.x = fmaxf(lo32(acc[i][0]) + be[0], 0.f);
        r0.y = fmaxf(lo32(acc[i][1]) + be[1], 0.f);
        r0.z = fmaxf(lo32(acc[i][2]) + be[2], 0.f);
        r0.w = fmaxf(lo32(acc[i][3]) + be[3], 0.f);
        r1.x = fmaxf(lo32(acc[i][4]) + be[4], 0.f);
        r1.y = fmaxf(lo32(acc[i][5]) + be[5], 0.f);
        r1.z = fmaxf(lo32(acc[i][6]) + be[6], 0.f);
        r1.w = fmaxf(lo32(acc[i][7]) + be[7], 0.f);
        s0.x = fmaxf(hi32(acc[i][0]) + be[0], 0.f);
        s0.y = fmaxf(hi32(acc[i][1]) + be[1], 0.f);
        s0.z = fmaxf(hi32(acc[i][2]) + be[2], 0.f);
        s0.w = fmaxf(hi32(acc[i][3]) + be[3], 0.f);
        s1.x = fmaxf(hi32(acc[i][4]) + be[4], 0.f);
        s1.y = fmaxf(hi32(acc[i][5]) + be[5], 0.f);
        s1.z = fmaxf(hi32(acc[i][6]) + be[6], 0.f);
        s1.w = fmaxf(hi32(acc[i][7]) + be[7], 0.f);
        *(float4*)(out0)     = r0;
        *(float4*)(out0 + 4) = r1;
        *(float4*)(out1)     = s0;
        *(float4*)(out1 + 4) = s1;
    }
}

// ============================================================================
// Kernel 2: exact top-64 per row, 2-pass 12-bit histogram select.
// Pass 1: histogram of (bits >> 20) with warp-aggregated smem atomics.
// Pass 2: collect strictly-greater values (< 64) + pivot-bin candidates
// (expected ~few for gaussian acts; capacity 2048). Exact rank select with
// (value desc, index asc) tie-break == jax.lax.top_k semantics.
// ============================================================================
__global__ void __launch_bounds__(256)
topk_kernel()
{
    __shared__ unsigned hist[4096];
    __shared__ unsigned csum[256];
    __shared__ int s_B, s_C, s_R;
    __shared__ unsigned s_nHi, s_nEq;
    __shared__ float cv[TOPK];
    __shared__ int   ci[TOPK];
    __shared__ unsigned eqV[2048];
    __shared__ int      eqI[2048];

    const int row = blockIdx.x;
    const int tid = threadIdx.x;
    const uint4* src = (const uint4*)(g_acts + (size_t)row * TDICT);

    for (int i = tid; i < 4096; i += 256) hist[i] = 0u;
    if (tid == 0) { s_nHi = 0u; s_nEq = 0u; }
    __syncthreads();

    // ---- pass 1: histogram ----
    for (int j = tid; j < TDICT / 4; j += 256) {
        uint4 v = src[j];
        unsigned bb[4] = {v.x >> 20, v.y >> 20, v.z >> 20, v.w >> 20};
        #pragma unroll
        for (int c = 0; c < 4; c++) {
            unsigned mk = __match_any_sync(0xffffffffu, bb[c]);
            if ((tid & 31) == (__ffs(mk) - 1))
                atomicAdd(&hist[bb[c]], (unsigned)__popc(mk));
        }
    }
    __syncthreads();

    // per-thread chunk sums (16 bins each)
    {
        unsigned s = 0;
        #pragma unroll
        for (int i = 0; i < 16; i++) s += hist[tid * 16 + i];
        csum[tid] = s;
    }
    __syncthreads();

    if (tid == 0) {
        int cum = 0, pc = 0;
        for (int t = 255; t >= 0; --t) {
            if (cum + (int)csum[t] >= TOPK) { pc = t; break; }
            cum += (int)csum[t];
        }
        int B = pc * 16;
        for (int i = 15; i >= 0; --i) {
            int h = (int)hist[pc * 16 + i];
            if (cum + h >= TOPK) { B = pc * 16 + i; break; }
            cum += h;
        }
        s_B = B; s_C = cum; s_R = TOPK - cum;
    }
    __syncthreads();

    const unsigned B = (unsigned)s_B;
    const int C = s_C, R = s_R;

    // ---- pass 2: collect ----
    for (int j = tid; j < TDICT / 4; j += 256) {
        uint4 v = src[j];
        unsigned vv[4] = {v.x, v.y, v.z, v.w};
        const int base = j * 4;
        #pragma unroll
        for (int c = 0; c < 4; c++) {
            unsigned bin = vv[c] >> 20;
            if (bin > B) {
                unsigned p = atomicAdd(&s_nHi, 1u);
                cv[p] = __uint_as_float(vv[c]);
                ci[p] = base + c;
            } else if (bin == B && B != 0u) {
                unsigned q = atomicAdd(&s_nEq, 1u);
                if (q < 2048u) { eqV[q] = vv[c]; eqI[q] = base + c; }
            }
        }
    }
    __syncthreads();

    if (B == 0u) {
        // fewer than 64 positive values: zero-valued fillers with sentinel idx
        if (tid < R) { cv[C + tid] = 0.f; ci[C + tid] = TDICT + tid; }
    } else {
        int nEq = (int)s_nEq; if (nEq > 2048) nEq = 2048;
        for (int t = tid; t < nEq; t += 256) {
            unsigned mv = eqV[t]; int mi = eqI[t];
            int rank = 0;
            for (int u = 0; u < nEq; ++u) {
                unsigned ov = eqV[u]; int oi = eqI[u];
                if (ov > mv || (ov == mv && oi < mi)) rank++;
            }
            if (rank < R) { cv[C + rank] = __uint_as_float(mv); ci[C + rank] = mi; }
        }
    }
    __syncthreads();

    // sort the 64 selected entries by index (all indices distinct)
    if (tid < TOPK) {
        int myI = ci[tid]; float myV = cv[tid];
        int rank = 0;
        #pragma unroll 8
        for (int u = 0; u < TOPK; ++u)
            if (ci[u] < myI) rank++;
        g_topv[row * TOPK + rank] = myV;
        g_topi[row * TOPK + rank] = (myI < TDICT) ? myI : 0;
    }
}

// ============================================================================
// Kernel 3: nested (matryoshka) sparse decode.
// ============================================================================
__global__ void __launch_bounds__(256)
decode_kernel(const float* __restrict__ Wdec, const float* __restrict__ Bdec,
              float* __restrict__ out)
{
    const int row = blockIdx.x;
    const int tid = threadIdx.x;
    __shared__ float sv[TOPK];
    __shared__ int   si[TOPK];
    if (tid < TOPK) {
        sv[tid] = g_topv[row * TOPK + tid];
        si[tid] = g_topi[row * TOPK + tid];
    }
    __syncthreads();

    const int d = tid * 4;
    float4 a0 = make_float4(0.f, 0.f, 0.f, 0.f);
    float4 a1 = a0, a2 = a0;

    #pragma unroll 4
    for (int e = 0; e < TOPK; ++e) {
        float v = sv[e];
        if (v == 0.f) continue;                 // filler / zero entry
        int idx = si[e];
        float4 w = *(const float4*)(Wdec + (size_t)idx * DIM + d);
        if (idx < G0_END) {
            a0.x += v * w.x; a0.y += v * w.y; a0.z += v * w.z; a0.w += v * w.w;
        } else if (idx < G1_END) {
            a1.x += v * w.x; a1.y += v * w.y; a1.z += v * w.z; a1.w += v * w.w;
        } else {
            a2.x += v * w.x; a2.y += v * w.y; a2.z += v * w.z; a2.w += v * w.w;
        }
    }

    float4 bd = *(const float4*)(Bdec + d);
    float4 r0 = make_float4(bd.x + a0.x, bd.y + a0.y, bd.z + a0.z, bd.w + a0.w);
    float4 r1 = make_float4(r0.x + a1.x, r0.y + a1.y, r0.z + a1.z, r0.w + a1.w);
    float4 r2 = make_float4(r1.x + a2.x, r1.y + a2.y, r1.z + a2.z, r1.w + a2.w);

    const size_t stride = (size_t)BATCH * DIM;
    float* o = out + (size_t)row * DIM + d;
    *(float4*)(o)              = r0;
    *(float4*)(o + stride)     = r1;
    *(float4*)(o + 2 * stride) = r2;
}

// ============================================================================
extern "C" void kernel_launch(void* const* d_in, const int* in_sizes, int n_in,
                              void* d_out, int out_size)
{
    const float* x     = (const float*)d_in[0];   // [4096, 1024]
    const float* W_enc = (const float*)d_in[1];   // [1024, 32768]
    const float* b_enc = (const float*)d_in[2];   // [32768]
    const float* W_dec = (const float*)d_in[3];   // [32768, 1024]
    const float* b_dec = (const float*)d_in[4];   // [1024]
    float* out = (float*)d_out;                   // [3, 4096, 1024]

    (void)in_sizes; (void)n_in; (void)out_size;

    dim3 ggrid(BATCH / 256, TDICT / 128);
    enc_gemm_relu<<<ggrid, 256>>>(x, W_enc, b_enc, b_dec);

    topk_kernel<<<BATCH, 256>>>();

    decode_kernel<<<BATCH, 256>>>(W_dec, b_dec, out);
}